// round 1
// baseline (speedup 1.0000x reference)
#include <cuda_runtime.h>
#include <cstddef>

#define NN   50000
#define NE   600000
#define DD   128
#define HH   256       // hidden width (=2*DD)
#define TE   64        // rows (edges/nodes) per CTA tile
#define KC   32        // K-chunk staged through smem
#define XPAD 260       // padded row stride for Xs (floats) -> conflict-free a-loads, 16B aligned

// scratch: aggregated messages per node (zeroed each launch)
__device__ float g_agg[(size_t)NN * DD];

// dynamic smem layout (floats):
//   Xs   : TE * XPAD        (input tile, later reused as hidden tile)
//   Ws   : KC * HH          (weight chunk; GEMM2 uses first KC*DD of it)
//   idx  : 2 * TE ints      (edge kernel only)
#define SMEM_FLOATS (TE * XPAD + KC * HH)
#define SMEM_BYTES  (SMEM_FLOATS * 4 + 2 * TE * 4)

__global__ void zero_agg_kernel() {
    const size_t n4 = (size_t)NN * DD / 4;
    float4 z = make_float4(0.f, 0.f, 0.f, 0.f);
    for (size_t i = (size_t)blockIdx.x * blockDim.x + threadIdx.x; i < n4;
         i += (size_t)gridDim.x * blockDim.x)
        reinterpret_cast<float4*>(g_agg)[i] = z;
}

// ---------------------------------------------------------------------------
// Edge (message) kernel: per 64-edge tile
//   X[r] = [feat[from[r]] , feat[to[r]]]           (64 x 256, smem)
//   H    = relu(X @ W0 + b0)                        (64 x 256, smem, reuses Xs)
//   M    = relu(H @ W1 + b1)                        (64 x 128, regs)
//   atomicAdd into g_agg[to[r]]
// Thread map: 256 threads, tx = tid&15 (16 col groups), ty = tid>>4 (16 row groups)
//   GEMM1: rows ty*4+i (i<4), cols tx+16*j (j<16)   -> acc[4][16]
//   GEMM2: rows ty*4+i,        cols tx+16*j (j<8)   -> acc2[4][8]
// ---------------------------------------------------------------------------
__global__ void __launch_bounds__(256, 2) msg_kernel(
    const float* __restrict__ feat,
    const int*   __restrict__ from_idx,
    const int*   __restrict__ to_idx,
    const float* __restrict__ W0, const float* __restrict__ b0,
    const float* __restrict__ W1, const float* __restrict__ b1)
{
    extern __shared__ float smem[];
    float (*Xs)[XPAD] = reinterpret_cast<float (*)[XPAD]>(smem);
    float* Ws   = smem + TE * XPAD;
    int*   s_fr = reinterpret_cast<int*>(Ws + KC * HH);
    int*   s_to = s_fr + TE;

    const int tid = threadIdx.x;
    const int tx  = tid & 15;
    const int ty  = tid >> 4;
    const int e0  = blockIdx.x * TE;

    if (tid < TE)            s_fr[tid]       = from_idx[e0 + tid];
    else if (tid < 2 * TE)   s_to[tid - TE]  = to_idx[e0 + tid - TE];
    __syncthreads();

    // ---- gather: 64 rows x 64 float4 = 4096 float4, 16 per thread ----
    const float4* feat4 = reinterpret_cast<const float4*>(feat);
    #pragma unroll
    for (int it = 0; it < 16; ++it) {
        int f4i = tid + it * 256;
        int r   = f4i >> 6;
        int c4  = f4i & 63;
        int src = (c4 < 32) ? s_fr[r] : s_to[r];
        int col = c4 & 31;
        float4 v = feat4[(size_t)src * 32 + col];
        *reinterpret_cast<float4*>(&Xs[r][c4 * 4]) = v;
    }
    __syncthreads();

    // ---- GEMM1: H = relu(X @ W0 + b0), 64x256, K=256 ----
    float acc[4][16];
    #pragma unroll
    for (int i = 0; i < 4; ++i)
        #pragma unroll
        for (int j = 0; j < 16; ++j) acc[i][j] = 0.f;

    for (int kk = 0; kk < HH; kk += KC) {
        // stage W0[kk:kk+32][0:256] -> Ws (2048 float4, 8 per thread)
        const float4* w4 = reinterpret_cast<const float4*>(W0 + kk * HH);
        #pragma unroll
        for (int i = 0; i < 8; ++i)
            reinterpret_cast<float4*>(Ws)[tid + i * 256] = w4[tid + i * 256];
        __syncthreads();

        #pragma unroll 4
        for (int k = 0; k < KC; ++k) {
            float a0 = Xs[ty * 4 + 0][kk + k];
            float a1 = Xs[ty * 4 + 1][kk + k];
            float a2 = Xs[ty * 4 + 2][kk + k];
            float a3 = Xs[ty * 4 + 3][kk + k];
            #pragma unroll
            for (int j = 0; j < 16; ++j) {
                float b = Ws[k * HH + tx + 16 * j];
                acc[0][j] += a0 * b;
                acc[1][j] += a1 * b;
                acc[2][j] += a2 * b;
                acc[3][j] += a3 * b;
            }
        }
        __syncthreads();
    }

    // write H (relu) back into Xs (conflict-free: banks span all 32)
    #pragma unroll
    for (int i = 0; i < 4; ++i)
        #pragma unroll
        for (int j = 0; j < 16; ++j) {
            float h = acc[i][j] + b0[tx + 16 * j];
            Xs[ty * 4 + i][tx + 16 * j] = fmaxf(h, 0.f);
        }

    // ---- GEMM2: M = relu(H @ W1 + b1), 64x128, K=256 ----
    float acc2[4][8];
    #pragma unroll
    for (int i = 0; i < 4; ++i)
        #pragma unroll
        for (int j = 0; j < 8; ++j) acc2[i][j] = 0.f;

    for (int kk = 0; kk < HH; kk += KC) {
        // stage W1[kk:kk+32][0:128] -> Ws (1024 float4, 4 per thread)
        const float4* w4 = reinterpret_cast<const float4*>(W1 + kk * DD);
        #pragma unroll
        for (int i = 0; i < 4; ++i)
            reinterpret_cast<float4*>(Ws)[tid + i * 256] = w4[tid + i * 256];
        __syncthreads();   // also orders H writes before first read

        #pragma unroll 4
        for (int k = 0; k < KC; ++k) {
            float a0 = Xs[ty * 4 + 0][kk + k];
            float a1 = Xs[ty * 4 + 1][kk + k];
            float a2 = Xs[ty * 4 + 2][kk + k];
            float a3 = Xs[ty * 4 + 3][kk + k];
            #pragma unroll
            for (int j = 0; j < 8; ++j) {
                float b = Ws[k * DD + tx + 16 * j];
                acc2[0][j] += a0 * b;
                acc2[1][j] += a1 * b;
                acc2[2][j] += a2 * b;
                acc2[3][j] += a3 * b;
            }
        }
        __syncthreads();
    }

    // ---- scatter: atomicAdd (RED.F32, no return) into g_agg[to] ----
    #pragma unroll
    for (int i = 0; i < 4; ++i) {
        int r   = ty * 4 + i;
        int dst = s_to[r];
        float* aggrow = g_agg + (size_t)dst * DD;
        #pragma unroll
        for (int j = 0; j < 8; ++j) {
            int   c = tx + 16 * j;
            float v = fmaxf(acc2[i][j] + b1[c], 0.f);
            atomicAdd(aggrow + c, v);
        }
    }
}

// ---------------------------------------------------------------------------
// Node update kernel: per 64-node tile
//   X[r] = [g_agg[n] , feat[n]]  -> relu(X@W0+b0) -> relu(@W1+b1) -> feat + h
// ---------------------------------------------------------------------------
__global__ void __launch_bounds__(256, 2) upd_kernel(
    const float* __restrict__ feat,
    const float* __restrict__ W0, const float* __restrict__ b0,
    const float* __restrict__ W1, const float* __restrict__ b1,
    float* __restrict__ out)
{
    extern __shared__ float smem[];
    float (*Xs)[XPAD] = reinterpret_cast<float (*)[XPAD]>(smem);
    float* Ws = smem + TE * XPAD;

    const int tid = threadIdx.x;
    const int tx  = tid & 15;
    const int ty  = tid >> 4;
    const int n0  = blockIdx.x * TE;

    // ---- gather [agg | feat] with tail guard ----
    const float4* feat4 = reinterpret_cast<const float4*>(feat);
    const float4* agg4  = reinterpret_cast<const float4*>(g_agg);
    #pragma unroll
    for (int it = 0; it < 16; ++it) {
        int f4i  = tid + it * 256;
        int r    = f4i >> 6;
        int c4   = f4i & 63;
        int node = n0 + r;
        float4 v = make_float4(0.f, 0.f, 0.f, 0.f);
        if (node < NN)
            v = (c4 < 32) ? agg4[(size_t)node * 32 + c4]
                          : feat4[(size_t)node * 32 + (c4 - 32)];
        *reinterpret_cast<float4*>(&Xs[r][c4 * 4]) = v;
    }
    __syncthreads();

    // ---- GEMM1 ----
    float acc[4][16];
    #pragma unroll
    for (int i = 0; i < 4; ++i)
        #pragma unroll
        for (int j = 0; j < 16; ++j) acc[i][j] = 0.f;

    for (int kk = 0; kk < HH; kk += KC) {
        const float4* w4 = reinterpret_cast<const float4*>(W0 + kk * HH);
        #pragma unroll
        for (int i = 0; i < 8; ++i)
            reinterpret_cast<float4*>(Ws)[tid + i * 256] = w4[tid + i * 256];
        __syncthreads();

        #pragma unroll 4
        for (int k = 0; k < KC; ++k) {
            float a0 = Xs[ty * 4 + 0][kk + k];
            float a1 = Xs[ty * 4 + 1][kk + k];
            float a2 = Xs[ty * 4 + 2][kk + k];
            float a3 = Xs[ty * 4 + 3][kk + k];
            #pragma unroll
            for (int j = 0; j < 16; ++j) {
                float b = Ws[k * HH + tx + 16 * j];
                acc[0][j] += a0 * b;
                acc[1][j] += a1 * b;
                acc[2][j] += a2 * b;
                acc[3][j] += a3 * b;
            }
        }
        __syncthreads();
    }

    #pragma unroll
    for (int i = 0; i < 4; ++i)
        #pragma unroll
        for (int j = 0; j < 16; ++j) {
            float h = acc[i][j] + b0[tx + 16 * j];
            Xs[ty * 4 + i][tx + 16 * j] = fmaxf(h, 0.f);
        }

    // ---- GEMM2 ----
    float acc2[4][8];
    #pragma unroll
    for (int i = 0; i < 4; ++i)
        #pragma unroll
        for (int j = 0; j < 8; ++j) acc2[i][j] = 0.f;

    for (int kk = 0; kk < HH; kk += KC) {
        const float4* w4 = reinterpret_cast<const float4*>(W1 + kk * DD);
        #pragma unroll
        for (int i = 0; i < 4; ++i)
            reinterpret_cast<float4*>(Ws)[tid + i * 256] = w4[tid + i * 256];
        __syncthreads();

        #pragma unroll 4
        for (int k = 0; k < KC; ++k) {
            float a0 = Xs[ty * 4 + 0][kk + k];
            float a1 = Xs[ty * 4 + 1][kk + k];
            float a2 = Xs[ty * 4 + 2][kk + k];
            float a3 = Xs[ty * 4 + 3][kk + k];
            #pragma unroll
            for (int j = 0; j < 8; ++j) {
                float b = Ws[k * DD + tx + 16 * j];
                acc2[0][j] += a0 * b;
                acc2[1][j] += a1 * b;
                acc2[2][j] += a2 * b;
                acc2[3][j] += a3 * b;
            }
        }
        __syncthreads();
    }

    // ---- epilogue: residual + store ----
    #pragma unroll
    for (int i = 0; i < 4; ++i) {
        int node = n0 + ty * 4 + i;
        if (node < NN) {
            const float* frow = feat + (size_t)node * DD;
            float*       orow = out  + (size_t)node * DD;
            #pragma unroll
            for (int j = 0; j < 8; ++j) {
                int   c = tx + 16 * j;
                float h = fmaxf(acc2[i][j] + b1[c], 0.f);
                orow[c] = frow[c] + h;
            }
        }
    }
}

extern "C" void kernel_launch(void* const* d_in, const int* in_sizes, int n_in,
                              void* d_out, int out_size)
{
    const float* feat   = (const float*)d_in[0];
    const int*   f_idx  = (const int*)  d_in[1];
    const int*   t_idx  = (const int*)  d_in[2];
    const float* msgW0  = (const float*)d_in[3];
    const float* msgb0  = (const float*)d_in[4];
    const float* msgW1  = (const float*)d_in[5];
    const float* msgb1  = (const float*)d_in[6];
    const float* updW0  = (const float*)d_in[7];
    const float* updb0  = (const float*)d_in[8];
    const float* updW1  = (const float*)d_in[9];
    const float* updb1  = (const float*)d_in[10];
    float* out = (float*)d_out;

    cudaFuncSetAttribute(msg_kernel, cudaFuncAttributeMaxDynamicSharedMemorySize, SMEM_BYTES);
    cudaFuncSetAttribute(upd_kernel, cudaFuncAttributeMaxDynamicSharedMemorySize, SMEM_BYTES);

    zero_agg_kernel<<<1024, 256>>>();
    msg_kernel<<<NE / TE, 256, SMEM_BYTES>>>(feat, f_idx, t_idx,
                                             msgW0, msgb0, msgW1, msgb1);
    upd_kernel<<<(NN + TE - 1) / TE, 256, SMEM_BYTES>>>(feat, updW0, updb0,
                                                        updW1, updb1, out);
}

// round 3
// speedup vs baseline: 2.3184x; 2.3184x over previous
#include <cuda_runtime.h>
#include <cuda_bf16.h>
#include <cstdint>
#include <cstddef>

#define NN 50000
#define NE 600000
#define DD 128
#define HH 256
#define TM 128

// ============================ device scratch ================================
__device__ float g_agg[(size_t)NN * DD];
// weights transposed to [N][K] row-major, bf16 hi/lo split
__device__ __nv_bfloat16 g_mW0h[HH * HH], g_mW0l[HH * HH];  // msg W0^T: [256][256]
__device__ __nv_bfloat16 g_mW1h[DD * HH], g_mW1l[DD * HH];  // msg W1^T: [128][256]
__device__ __nv_bfloat16 g_uW0h[HH * HH], g_uW0l[HH * HH];
__device__ __nv_bfloat16 g_uW1h[DD * HH], g_uW1l[DD * HH];

// ============================ smem layout (bytes) ===========================
// A tiles: 128 rows x 264 halves (528 B row stride, 33x16B -> conflict-free)
// B tiles: 256 rows x  72 halves (144 B row stride,  9x16B -> conflict-free)
#define SM_B0   0                     // 256 floats
#define SM_B1   1024                  // 128 floats
#define SM_FR   1536                  // 128 ints
#define SM_TO   2048                  // 128 ints
#define SM_AHI  4096
#define SM_ALO  (4096 + 67584)        // 71680
#define SM_BH   (71680 + 67584)       // 139264
#define SM_BL   (139264 + 36864)      // 176128
#define SMEM_TOTAL (176128 + 36864)   // 212992
#define AROW 528
#define BROW 144

// ============================ PTX helpers ===================================
__device__ __forceinline__ uint32_t smem_u32(const void* p) {
    uint32_t a;
    asm("{ .reg .u64 t; cvta.to.shared.u64 t, %1; cvt.u32.u64 %0, t; }" : "=r"(a) : "l"(p));
    return a;
}
__device__ __forceinline__ void ldsm_x4(uint32_t& r0, uint32_t& r1, uint32_t& r2,
                                        uint32_t& r3, uint32_t addr) {
    asm volatile("ldmatrix.sync.aligned.m8n8.x4.shared.b16 {%0,%1,%2,%3}, [%4];"
                 : "=r"(r0), "=r"(r1), "=r"(r2), "=r"(r3) : "r"(addr));
}
__device__ __forceinline__ void mma_bf16(float* d, const uint32_t* a,
                                         uint32_t b0, uint32_t b1) {
    asm volatile(
        "mma.sync.aligned.m16n8k16.row.col.f32.bf16.bf16.f32 "
        "{%0,%1,%2,%3},{%4,%5,%6,%7},{%8,%9},{%0,%1,%2,%3};"
        : "+f"(d[0]), "+f"(d[1]), "+f"(d[2]), "+f"(d[3])
        : "r"(a[0]), "r"(a[1]), "r"(a[2]), "r"(a[3]), "r"(b0), "r"(b1));
}
__device__ __forceinline__ uint32_t pack_bf16(float a, float b) {
    __nv_bfloat162 t = __floats2bfloat162_rn(a, b);
    return *reinterpret_cast<uint32_t*>(&t);
}

// =========================== prelude kernels ================================
__global__ void zero_agg_kernel() {
    const size_t n4 = (size_t)NN * DD / 4;
    float4 z = make_float4(0.f, 0.f, 0.f, 0.f);
    for (size_t i = (size_t)blockIdx.x * blockDim.x + threadIdx.x; i < n4;
         i += (size_t)gridDim.x * blockDim.x)
        reinterpret_cast<float4*>(g_agg)[i] = z;
}

__device__ __forceinline__ void put_split(__nv_bfloat16* h, __nv_bfloat16* l,
                                          int idx, float w) {
    __nv_bfloat16 hi = __float2bfloat16(w);
    h[idx] = hi;
    l[idx] = __float2bfloat16(w - __bfloat162float(hi));
}

// W (row-major [K][N]) -> transposed [N][K] hi/lo
__global__ void conv_w_kernel(const float* __restrict__ mW0, const float* __restrict__ uW0,
                              const float* __restrict__ mW1, const float* __restrict__ uW1) {
    int i = blockIdx.x * blockDim.x + threadIdx.x;
    if (i >= 196608) return;
    if (i < 65536) {
        int k = i >> 8, n = i & 255;
        put_split(g_mW0h, g_mW0l, n * HH + k, mW0[i]);
    } else if (i < 131072) {
        int j = i - 65536, k = j >> 8, n = j & 255;
        put_split(g_uW0h, g_uW0l, n * HH + k, uW0[j]);
    } else if (i < 163840) {
        int j = i - 131072, k = j >> 7, n = j & 127;
        put_split(g_mW1h, g_mW1l, n * HH + k, mW1[j]);
    } else {
        int j = i - 163840, k = j >> 7, n = j & 127;
        put_split(g_uW1h, g_uW1l, n * HH + k, uW1[j]);
    }
}

// ============================ main MLP kernel ===============================
// is_edge=1: X=[feat[from]|feat[to]] -> msg MLP -> atomicAdd into g_agg[to]
// is_edge=0: X=[g_agg[n]|feat[n]]    -> upd MLP -> out = feat + h
__global__ void __launch_bounds__(512, 1) mlp_kernel(
    int is_edge, const float* __restrict__ feat,
    const int* __restrict__ from_idx, const int* __restrict__ to_idx,
    const float* __restrict__ b0, const float* __restrict__ b1,
    float* __restrict__ outp)
{
    extern __shared__ char smc[];
    const uint32_t sb = smem_u32(smc);
    const int tid  = threadIdx.x;
    const int wid  = tid >> 5;
    const int lane = tid & 31;
    const int wr   = wid & 3;   // row group: rows wr*32..+32
    const int wc   = wid >> 2;  // col group
    // ldmatrix per-lane offsets (quad j = lane>>3): row += (j&1)*8, col += (j>>1)*8
    const int lrow = ((lane >> 3) & 1) * 8 + (lane & 7);
    const int lcol = (lane >> 4) * 8;

    float* b0s = reinterpret_cast<float*>(smc + SM_B0);
    float* b1s = reinterpret_cast<float*>(smc + SM_B1);
    int*   sfr = reinterpret_cast<int*>(smc + SM_FR);
    int*   sto = reinterpret_cast<int*>(smc + SM_TO);

    const int tile0 = blockIdx.x * TM;
    const int total = is_edge ? NE : NN;
    const int rem   = min(TM, total - tile0);

    if (tid < 256) b0s[tid] = b0[tid];
    if (tid < 128) b1s[tid] = b1[tid];
    if (is_edge && tid < 128) {
        int e = tile0 + tid;
        sfr[tid] = (tid < rem) ? from_idx[e] : 0;
        sto[tid] = (tid < rem) ? to_idx[e] : 0;
    }
    __syncthreads();

    // ---- gather X [128 x 256] fp32 -> bf16 hi/lo into A tiles --------------
    {
        const float4* f4 = reinterpret_cast<const float4*>(feat);
        const float4* a4 = reinterpret_cast<const float4*>(g_agg);
        #pragma unroll
        for (int it = 0; it < 16; ++it) {
            int ci = tid + it * 512;
            int r  = ci >> 6;
            int c4 = ci & 63;
            float4 v = make_float4(0.f, 0.f, 0.f, 0.f);
            if (is_edge) {
                int src = (c4 < 32) ? sfr[r] : sto[r];
                v = f4[(size_t)src * 32 + (c4 & 31)];
            } else {
                int node = tile0 + r;
                if (node < NN)
                    v = (c4 < 32) ? a4[(size_t)node * 32 + c4]
                                  : f4[(size_t)node * 32 + (c4 - 32)];
            }
            __nv_bfloat16 h0 = __float2bfloat16(v.x), h1 = __float2bfloat16(v.y);
            __nv_bfloat16 h2 = __float2bfloat16(v.z), h3 = __float2bfloat16(v.w);
            uint2 H, L;
            H.x = pack_bf16(v.x, v.y);  // NB: pack_bf16 re-rounds; identical to h0,h1
            H.y = pack_bf16(v.z, v.w);
            L.x = pack_bf16(v.x - __bfloat162float(h0), v.y - __bfloat162float(h1));
            L.y = pack_bf16(v.z - __bfloat162float(h2), v.w - __bfloat162float(h3));
            int off = r * AROW + c4 * 8;
            *reinterpret_cast<uint2*>(smc + SM_AHI + off) = H;
            *reinterpret_cast<uint2*>(smc + SM_ALO + off) = L;
        }
    }
    __syncthreads();

    const __nv_bfloat16* W0h = is_edge ? g_mW0h : g_uW0h;
    const __nv_bfloat16* W0l = is_edge ? g_mW0l : g_uW0l;
    const __nv_bfloat16* W1h = is_edge ? g_mW1h : g_uW1h;
    const __nv_bfloat16* W1l = is_edge ? g_mW1l : g_uW1l;

    // ======================= GEMM1: H = relu(X@W0+b0) =======================
    float acc[2][8][4];
    #pragma unroll
    for (int m = 0; m < 2; ++m)
        #pragma unroll
        for (int n = 0; n < 8; ++n)
            #pragma unroll
            for (int q = 0; q < 4; ++q) acc[m][n][q] = 0.f;

    for (int kc = 0; kc < 4; ++kc) {
        // stage W0^T[:, kc*64 : +64] hi/lo -> Bs (256 rows x 64 halves)
        {
            const uint4* srcH = reinterpret_cast<const uint4*>(W0h);
            const uint4* srcL = reinterpret_cast<const uint4*>(W0l);
            #pragma unroll
            for (int i = 0; i < 4; ++i) {
                int idx = tid + i * 512;          // 0..2047
                int row = idx >> 3, seg = idx & 7;
                int dst = row * BROW + seg * 16;
                int src = row * 32 + kc * 8 + seg;
                *reinterpret_cast<uint4*>(smc + SM_BH + dst) = srcH[src];
                *reinterpret_cast<uint4*>(smc + SM_BL + dst) = srcL[src];
            }
        }
        __syncthreads();

        #pragma unroll
        for (int ks = 0; ks < 4; ++ks) {
            const int kA = kc * 64 + ks * 16;
            const int kB = ks * 16;
            uint32_t ah[2][4], al[2][4];
            #pragma unroll
            for (int mt = 0; mt < 2; ++mt) {
                uint32_t aaddr = sb + SM_AHI +
                    (uint32_t)((wr * 32 + mt * 16 + lrow) * AROW + (kA + lcol) * 2);
                ldsm_x4(ah[mt][0], ah[mt][1], ah[mt][2], ah[mt][3], aaddr);
                ldsm_x4(al[mt][0], al[mt][1], al[mt][2], al[mt][3],
                        aaddr + (SM_ALO - SM_AHI));
            }
            #pragma unroll
            for (int np = 0; np < 4; ++np) {
                uint32_t baddr = sb + SM_BH +
                    (uint32_t)((wc * 64 + np * 16 + lrow) * BROW + (kB + lcol) * 2);
                uint32_t bh0, bh1, bh2, bh3, bl0, bl1, bl2, bl3;
                ldsm_x4(bh0, bh1, bh2, bh3, baddr);
                ldsm_x4(bl0, bl1, bl2, bl3, baddr + (SM_BL - SM_BH));
                #pragma unroll
                for (int mt = 0; mt < 2; ++mt) {
                    mma_bf16(acc[mt][2 * np],     ah[mt], bh0, bh2);
                    mma_bf16(acc[mt][2 * np + 1], ah[mt], bh1, bh3);
                    mma_bf16(acc[mt][2 * np],     al[mt], bh0, bh2);
                    mma_bf16(acc[mt][2 * np + 1], al[mt], bh1, bh3);
                    mma_bf16(acc[mt][2 * np],     ah[mt], bl0, bl2);
                    mma_bf16(acc[mt][2 * np + 1], ah[mt], bl1, bl3);
                }
            }
        }
        __syncthreads();
    }

    // ---- epilogue1: bias+relu, hi/lo split, write H back into A tiles ------
    #pragma unroll
    for (int mt = 0; mt < 2; ++mt)
        #pragma unroll
        for (int nt = 0; nt < 8; ++nt) {
            int c  = wc * 64 + nt * 8 + 2 * (lane & 3);
            int r0 = wr * 32 + mt * 16 + (lane >> 2);
            float* d = acc[mt][nt];
            float v0 = fmaxf(d[0] + b0s[c], 0.f), v1 = fmaxf(d[1] + b0s[c + 1], 0.f);
            float v2 = fmaxf(d[2] + b0s[c], 0.f), v3 = fmaxf(d[3] + b0s[c + 1], 0.f);
            __nv_bfloat16 h0 = __float2bfloat16(v0), h1 = __float2bfloat16(v1);
            __nv_bfloat16 h2 = __float2bfloat16(v2), h3 = __float2bfloat16(v3);
            int o0 = r0 * AROW + c * 2;
            int o1 = (r0 + 8) * AROW + c * 2;
            *reinterpret_cast<uint32_t*>(smc + SM_AHI + o0) = pack_bf16(v0, v1);
            *reinterpret_cast<uint32_t*>(smc + SM_AHI + o1) = pack_bf16(v2, v3);
            *reinterpret_cast<uint32_t*>(smc + SM_ALO + o0) =
                pack_bf16(v0 - __bfloat162float(h0), v1 - __bfloat162float(h1));
            *reinterpret_cast<uint32_t*>(smc + SM_ALO + o1) =
                pack_bf16(v2 - __bfloat162float(h2), v3 - __bfloat162float(h3));
        }

    // ======================= GEMM2: M = relu(H@W1+b1) =======================
    float ac2[2][4][4];
    #pragma unroll
    for (int m = 0; m < 2; ++m)
        #pragma unroll
        for (int n = 0; n < 4; ++n)
            #pragma unroll
            for (int q = 0; q < 4; ++q) ac2[m][n][q] = 0.f;

    for (int kc = 0; kc < 4; ++kc) {
        {
            const uint4* srcH = reinterpret_cast<const uint4*>(W1h);
            const uint4* srcL = reinterpret_cast<const uint4*>(W1l);
            #pragma unroll
            for (int i = 0; i < 2; ++i) {
                int idx = tid + i * 512;          // 0..1023
                int row = idx >> 3, seg = idx & 7;
                int dst = row * BROW + seg * 16;
                int src = row * 32 + kc * 8 + seg;
                *reinterpret_cast<uint4*>(smc + SM_BH + dst) = srcH[src];
                *reinterpret_cast<uint4*>(smc + SM_BL + dst) = srcL[src];
            }
        }
        __syncthreads();

        #pragma unroll
        for (int ks = 0; ks < 4; ++ks) {
            const int kA = kc * 64 + ks * 16;
            const int kB = ks * 16;
            uint32_t ah[2][4], al[2][4];
            #pragma unroll
            for (int mt = 0; mt < 2; ++mt) {
                uint32_t aaddr = sb + SM_AHI +
                    (uint32_t)((wr * 32 + mt * 16 + lrow) * AROW + (kA + lcol) * 2);
                ldsm_x4(ah[mt][0], ah[mt][1], ah[mt][2], ah[mt][3], aaddr);
                ldsm_x4(al[mt][0], al[mt][1], al[mt][2], al[mt][3],
                        aaddr + (SM_ALO - SM_AHI));
            }
            #pragma unroll
            for (int np = 0; np < 2; ++np) {
                uint32_t baddr = sb + SM_BH +
                    (uint32_t)((wc * 32 + np * 16 + lrow) * BROW + (kB + lcol) * 2);
                uint32_t bh0, bh1, bh2, bh3, bl0, bl1, bl2, bl3;
                ldsm_x4(bh0, bh1, bh2, bh3, baddr);
                ldsm_x4(bl0, bl1, bl2, bl3, baddr + (SM_BL - SM_BH));
                #pragma unroll
                for (int mt = 0; mt < 2; ++mt) {
                    mma_bf16(ac2[mt][2 * np],     ah[mt], bh0, bh2);
                    mma_bf16(ac2[mt][2 * np + 1], ah[mt], bh1, bh3);
                    mma_bf16(ac2[mt][2 * np],     al[mt], bh0, bh2);
                    mma_bf16(ac2[mt][2 * np + 1], al[mt], bh1, bh3);
                    mma_bf16(ac2[mt][2 * np],     ah[mt], bl0, bl2);
                    mma_bf16(ac2[mt][2 * np + 1], ah[mt], bl1, bl3);
                }
            }
        }
        __syncthreads();
    }

    // ---- epilogue2: bias+relu, scatter-atomic / residual store -------------
    #pragma unroll
    for (int mt = 0; mt < 2; ++mt)
        #pragma unroll
        for (int nt = 0; nt < 4; ++nt) {
            int c  = wc * 32 + nt * 8 + 2 * (lane & 3);
            int r0 = wr * 32 + mt * 16 + (lane >> 2);
            int r1 = r0 + 8;
            float* d = ac2[mt][nt];
            float v0 = fmaxf(d[0] + b1s[c], 0.f), v1 = fmaxf(d[1] + b1s[c + 1], 0.f);
            float v2 = fmaxf(d[2] + b1s[c], 0.f), v3 = fmaxf(d[3] + b1s[c + 1], 0.f);
            if (is_edge) {
                if (r0 < rem) {
                    float* a = g_agg + (size_t)sto[r0] * DD + c;
                    atomicAdd(a, v0);
                    atomicAdd(a + 1, v1);
                }
                if (r1 < rem) {
                    float* a = g_agg + (size_t)sto[r1] * DD + c;
                    atomicAdd(a, v2);
                    atomicAdd(a + 1, v3);
                }
            } else {
                int n0 = tile0 + r0, n1 = tile0 + r1;
                if (n0 < NN) {
                    float2 f = *reinterpret_cast<const float2*>(feat + (size_t)n0 * DD + c);
                    float2 o = make_float2(f.x + v0, f.y + v1);
                    *reinterpret_cast<float2*>(outp + (size_t)n0 * DD + c) = o;
                }
                if (n1 < NN) {
                    float2 f = *reinterpret_cast<const float2*>(feat + (size_t)n1 * DD + c);
                    float2 o = make_float2(f.x + v2, f.y + v3);
                    *reinterpret_cast<float2*>(outp + (size_t)n1 * DD + c) = o;
                }
            }
        }
}

// ============================== host launch =================================
extern "C" void kernel_launch(void* const* d_in, const int* in_sizes, int n_in,
                              void* d_out, int out_size)
{
    const float* feat  = (const float*)d_in[0];
    const int*   f_idx = (const int*)  d_in[1];
    const int*   t_idx = (const int*)  d_in[2];
    const float* msgW0 = (const float*)d_in[3];
    const float* msgb0 = (const float*)d_in[4];
    const float* msgW1 = (const float*)d_in[5];
    const float* msgb1 = (const float*)d_in[6];
    const float* updW0 = (const float*)d_in[7];
    const float* updb0 = (const float*)d_in[8];
    const float* updW1 = (const float*)d_in[9];
    const float* updb1 = (const float*)d_in[10];
    float* out = (float*)d_out;

    cudaFuncSetAttribute(mlp_kernel, cudaFuncAttributeMaxDynamicSharedMemorySize, SMEM_TOTAL);

    conv_w_kernel<<<768, 256>>>(msgW0, updW0, msgW1, updW1);
    zero_agg_kernel<<<1024, 256>>>();

    const int edge_tiles = (NE + TM - 1) / TM;  // 4688
    const int node_tiles = (NN + TM - 1) / TM;  // 391
    mlp_kernel<<<edge_tiles, 512, SMEM_TOTAL>>>(1, feat, f_idx, t_idx, msgb0, msgb1, nullptr);
    mlp_kernel<<<node_tiles, 512, SMEM_TOTAL>>>(0, feat, f_idx, t_idx, updb0, updb1, out);
}